// round 15
// baseline (speedup 1.0000x reference)
#include <cuda_runtime.h>
#include <cuda_bf16.h>
#include <math.h>

// Problem constants
#define BSZ   8
#define MROW  64
#define NCOL  4096
#define KSEL  32
#define NPAIR (BSZ * MROW)        // 512 (b,m) pairs
#define NROWS (NPAIR * KSEL)      // 16384 output rows
#define TPB   256                 // 8 warps
#define VPT   16                  // logits per thread (4096/256)
#define NBKT  4096                // histogram buckets (top 12 bits of fmap)
#define CAP   2048                // candidate cap (expected ~100)

// Noise bounds: gn = -0.001*log(-log(u+1e-20)+1e-20) in [-0.003830, +0.046052],
// span < 0.04989 -> margin 0.06 is strictly safe.
#define MARGIN 0.06f

// Static scratch (no allocation allowed). Self-cleaning across launches:
// g_flag/g_done return to 0 at the end of every launch (see consumer code).
__device__ int g_idx[NROWS];
__device__ int g_flag[NPAIR];
__device__ int g_done[NPAIR];

// Order-preserving float->uint map: a > b  <=>  fmap(a) > fmap(b). Bijective.
__device__ __forceinline__ unsigned fmap(float f) {
    unsigned b = __float_as_uint(f);
    return b ^ ((unsigned)(((int)b) >> 31) | 0x80000000u);
}
__device__ __forceinline__ float unfmap(unsigned m) {
    unsigned b = (m & 0x80000000u) ? (m ^ 0x80000000u) : ~m;
    return __uint_as_float(b);
}

// ---------------------------------------------------------------------------
// Split-grid fused kernel: grid = NPAIR + NROWS.
//   blocks [0, 512):   SELECT-ONLY for bm = b; release flag; retire fast.
//   blocks [512, ...): FILL-ONLY, warp-specialized: warp 0 polls the flag
//                      WHILE warps 1-7 write the zeros; then one 1.0 store.
// Select blocks have the lowest bids -> guaranteed wave 1 -> no deadlock.
// The 32nd consumer of each bm resets flag+counter (graph-replay safe;
// every consumer increments only after passing its poll, so the reset can
// never strand a poller).
// ---------------------------------------------------------------------------
__global__ __launch_bounds__(TPB, 8)
void fused_kernel(const float* __restrict__ logits,
                  const float* __restrict__ u,
                  float* __restrict__ out)
{
    const int b = blockIdx.x;
    const int t = threadIdx.x;

    if (b < NPAIR) {
        // =================== SELECT-ONLY for bm = b ========================
        // hist dead before keys are written -> overlay (16 KB), 16B-aligned
        // for the int4 zero-fill stores.
        __shared__ __align__(16) union {
            int                s_hist[NBKT];
            unsigned long long s_keys[CAP];
        } ov;
        __shared__ int s_top[KSEL];
        __shared__ int s_cnt;
        __shared__ int s_bkt;

        const int bm   = b;
        const int m    = bm & (MROW - 1);
        const int lane = t & 31;
        const int warp = t >> 5;

        // ---- Load logits row straight into mapped-uint domain ----
        const int base = t * VPT;
        const float4* __restrict__ l4 = (const float4*)(logits + (size_t)m * NCOL);
        unsigned um[VPT];
#pragma unroll
        for (int q = 0; q < 4; q++) {
            float4 ll = l4[(base >> 2) + q];
            um[q*4+0] = fmap(ll.x); um[q*4+1] = fmap(ll.y);
            um[q*4+2] = fmap(ll.z); um[q*4+3] = fmap(ll.w);
        }

        // ---- Zero histogram ----
#pragma unroll
        for (int i = 0; i < NBKT / (TPB * 4); i++)
            ((int4*)ov.s_hist)[t + i * TPB] = make_int4(0, 0, 0, 0);
        if (t == 0) s_cnt = 0;

        // ---- Prefilter: thread max only (1 atomic/thread; 256 counted real
        //      values >= 32 -> threshold conservative -> still exact) ----
        unsigned mx = um[0];
#pragma unroll
        for (int j = 1; j < VPT; j++) mx = max(mx, um[j]);
        __syncthreads();                     // hist zeroed
        atomicAdd(&ov.s_hist[mx >> 20], 1);
        __syncthreads();

        // ---- Warp 0: chunk scan for bucket where counted-cum reaches 32 ----
        if (warp == 0) {
            const unsigned FULL = 0xffffffffu;
            int cum = 0;
            for (int bb = NBKT - 64; bb >= 0; bb -= 64) {
                const int2 c = ((const int2*)(ov.s_hist + bb))[lane];
                const int pair  = c.x + c.y;
                const int total = __reduce_add_sync(FULL, pair);
                if (cum + total >= KSEL) {
                    int suf = pair;          // inclusive suffix sum over lanes
#pragma unroll
                    for (int off = 1; off < 32; off <<= 1) {
                        const int o = __shfl_down_sync(FULL, suf, off);
                        if (lane + off < 32) suf += o;
                    }
                    const int cx = cum + suf;
                    const unsigned bal = __ballot_sync(FULL, cx >= KSEL);
                    const int hi = 31 - __clz(bal);
                    if (lane == hi) {
                        const int cy = cx - c.x;
                        s_bkt = bb + lane * 2 + ((cy >= KSEL) ? 1 : 0);
                    }
                    break;
                }
                cum += total;
            }
        }
        __syncthreads();   // s_bkt ready; hist dead (union -> keys)

        // ---- Gather: mapped compare; u-load + Gumbel key only for ~100 ----
        const unsigned thrm = fmap(unfmap((unsigned)s_bkt << 20) - MARGIN);
        const float* __restrict__ urow = u + (size_t)bm * NCOL;
#pragma unroll
        for (int j = 0; j < VPT; j++) {
            if (um[j] >= thrm) {
                const int pos = atomicAdd(&s_cnt, 1);
                if (pos < CAP) {
                    const int idx = base + j;
                    const float u2 = urow[idx];
                    const float gn = -0.001f * __logf(-__logf(u2 + 1e-20f) + 1e-20f);
                    const float val = unfmap(um[j]) + gn;
                    // unique key; larger value wins, ties -> lower index
                    ov.s_keys[pos] = ((unsigned long long)fmap(val) << 32)
                                   | (unsigned)(~idx);
                }
            }
        }
        __syncthreads();

        // ---- Parallel rank-count top-32 (all 256 threads) ----
        const int cnt = min(s_cnt, CAP);     // >= KSEL by construction
        for (int i = t; i < cnt; i += TPB) {
            const unsigned long long k = ov.s_keys[i];
            int r = 0;
            for (int j = 0; j < cnt; j++)
                r += (ov.s_keys[j] > k) ? 1 : 0;   // unique keys -> unique ranks
            if (r < KSEL) s_top[r] = (int)(~(unsigned)k);
        }
        __syncthreads();

        // ---- Index-rank sort -> ascending; publish + release flag ----
        if (t < KSEL) {
            const int myidx = s_top[t];
            int rank = 0;
#pragma unroll
            for (int j = 0; j < KSEL; j++) rank += (s_top[j] < myidx) ? 1 : 0;
            g_idx[bm * KSEL + rank] = myidx;
            __threadfence();                 // release (512 blocks only: cheap)
        }
        __syncthreads();
        if (t == 0) atomicExch(&g_flag[bm], 1);
        return;                              // retire fast, free the slot
    }

    // ====================== FILL-ONLY block (warp-specialized) =============
    const int f    = b - NPAIR;              // 0..16383
    const int bmf  = f & (NPAIR - 1);
    const int sub  = f >> 9;
    const int row  = bmf * KSEL + sub;

    __shared__ int s_target;

    float4* __restrict__ o = reinterpret_cast<float4*>(out + (size_t)row * NCOL);

    if (t < 32) {
        // ---- Warp 0: poll concurrently with the stores below ----
        if (t == 0) {
            unsigned v;
            // first try without sleeping (flag almost always already set)
            asm volatile("ld.global.acquire.gpu.b32 %0, [%1];"
                         : "=r"(v) : "l"(&g_flag[bmf]) : "memory");
            while (!v) {
                __nanosleep(32);
                asm volatile("ld.global.acquire.gpu.b32 %0, [%1];"
                             : "=r"(v) : "l"(&g_flag[bmf]) : "memory");
            }
            s_target = g_idx[row];
        }
    } else {
        // ---- Warps 1-7: all 1024 float4 slots of zeros (224 threads x 5) --
        const int ti = t - 32;               // 0..223
        const float4 z = make_float4(0.f, 0.f, 0.f, 0.f);
#pragma unroll
        for (int i = 0; i < 5; i++) {
            const int slot = ti + i * 224;   // 0..1119
            if (slot < 1024) o[slot] = z;
        }
    }
    __syncthreads();               // zeros ordered before the 1.0 store
    if (t == 0) {
        out[(size_t)row * NCOL + s_target] = 1.0f;
        // 32 consumers per bm; the last resets sync state (replay-safe).
        // Off the store critical path: warps 1-7 have already exited.
        const int old = atomicAdd(&g_done[bmf], 1);
        if (old == KSEL - 1) {
            atomicExch(&g_flag[bmf], 0);
            atomicExch(&g_done[bmf], 0);
        }
    }
}

extern "C" void kernel_launch(void* const* d_in, const int* in_sizes, int n_in,
                              void* d_out, int out_size)
{
    const float* logits = (const float*)d_in[0];   // (64, 4096) fp32
    const float* u      = (const float*)d_in[1];   // (8, 64, 4096) fp32
    float*       out    = (float*)d_out;           // (8, 64, 32, 4096) fp32

    fused_kernel<<<NPAIR + NROWS, TPB>>>(logits, u, out);
}

// round 16
// speedup vs baseline: 1.0668x; 1.0668x over previous
#include <cuda_runtime.h>
#include <cuda_bf16.h>
#include <math.h>

// Problem constants
#define BSZ   8
#define MROW  64
#define NCOL  4096
#define KSEL  32
#define NPAIR (BSZ * MROW)        // 512 (b,m) pairs
#define NROWS (NPAIR * KSEL)      // 16384 output rows
#define TPB   256                 // 8 warps
#define VPT   16                  // logits per thread (4096/256)
#define NBKT  4096                // histogram buckets (top 12 bits of fmap)
#define CAP   2048                // candidate cap (expected ~100)

// Noise bounds: gn = -0.001*log(-log(u+1e-20)+1e-20) in [-0.003830, +0.046052],
// span < 0.04989 -> margin 0.06 is strictly safe.
#define MARGIN 0.06f

// Static scratch (no allocation allowed). Self-cleaning across launches:
// g_flag/g_done return to 0 at the end of every launch (last-consumer reset).
__device__ int g_idx[NROWS];
__device__ int g_flag[NPAIR];
__device__ int g_done[NPAIR];

// Order-preserving float->uint map: a > b  <=>  fmap(a) > fmap(b). Bijective.
__device__ __forceinline__ unsigned fmap(float f) {
    unsigned b = __float_as_uint(f);
    return b ^ ((unsigned)(((int)b) >> 31) | 0x80000000u);
}
__device__ __forceinline__ float unfmap(unsigned m) {
    unsigned b = (m & 0x80000000u) ? (m ^ 0x80000000u) : ~m;
    return __uint_as_float(b);
}

// Scoped atomics (no CCTL.IVALL, unlike __threadfence)
__device__ __forceinline__ int atom_add_acqrel(int* p, int v) {
    int old;
    asm volatile("atom.acq_rel.gpu.global.add.s32 %0, [%1], %2;"
                 : "=r"(old) : "l"(p), "r"(v) : "memory");
    return old;
}
__device__ __forceinline__ void atom_exch_release(int* p, int v) {
    int old;
    asm volatile("atom.release.gpu.global.exch.b32 %0, [%1], %2;"
                 : "=r"(old) : "l"(p), "r"(v) : "memory");
}
__device__ __forceinline__ int ld_acquire(const int* p) {
    int v;
    asm volatile("ld.acquire.gpu.global.b32 %0, [%1];"
                 : "=r"(v) : "l"(p) : "memory");
    return v;
}

// ---------------------------------------------------------------------------
// Split-grid fused kernel: grid = NPAIR + NROWS.
//   blocks [0, 512):   SELECT-ONLY for bm = b; release flag; retire fast.
//   blocks [512, ...): FILL-ONLY: zeros -> one acq_rel counter atomic.
//                      The LAST fill block per bm (old == 31) alone polls the
//                      flag and writes all 32 scattered 1.0s, then resets
//                      flag+counter (graph-replay safe).
// Ordering: each block's release-add orders its zeros before the increment;
// the last block's acquire-add synchronizes with all 31 releases, so every
// zero of the bm is visible before any 1.0 of the bm is stored.
// ---------------------------------------------------------------------------
__global__ __launch_bounds__(TPB, 8)
void fused_kernel(const float* __restrict__ logits,
                  const float* __restrict__ u,
                  float* __restrict__ out)
{
    const int b = blockIdx.x;
    const int t = threadIdx.x;

    if (b < NPAIR) {
        // =================== SELECT-ONLY for bm = b ========================
        // hist dead before keys are written -> overlay (16 KB), 16B-aligned
        // for the int4 zero-fill stores.
        __shared__ __align__(16) union {
            int                s_hist[NBKT];
            unsigned long long s_keys[CAP];
        } ov;
        __shared__ int s_top[KSEL];
        __shared__ int s_cnt;
        __shared__ int s_bkt;

        const int bm   = b;
        const int m    = bm & (MROW - 1);
        const int lane = t & 31;
        const int warp = t >> 5;

        // ---- Load logits row straight into mapped-uint domain ----
        const int base = t * VPT;
        const float4* __restrict__ l4 = (const float4*)(logits + (size_t)m * NCOL);
        unsigned um[VPT];
#pragma unroll
        for (int q = 0; q < 4; q++) {
            float4 ll = l4[(base >> 2) + q];
            um[q*4+0] = fmap(ll.x); um[q*4+1] = fmap(ll.y);
            um[q*4+2] = fmap(ll.z); um[q*4+3] = fmap(ll.w);
        }

        // ---- Zero histogram ----
#pragma unroll
        for (int i = 0; i < NBKT / (TPB * 4); i++)
            ((int4*)ov.s_hist)[t + i * TPB] = make_int4(0, 0, 0, 0);
        if (t == 0) s_cnt = 0;

        // ---- Prefilter: thread max only (1 atomic/thread; 256 counted real
        //      values >= 32 -> threshold conservative -> still exact) ----
        unsigned mx = um[0];
#pragma unroll
        for (int j = 1; j < VPT; j++) mx = max(mx, um[j]);
        __syncthreads();                     // hist zeroed
        atomicAdd(&ov.s_hist[mx >> 20], 1);
        __syncthreads();

        // ---- Warp 0: chunk scan for bucket where counted-cum reaches 32 ----
        if (warp == 0) {
            const unsigned FULL = 0xffffffffu;
            int cum = 0;
            for (int bb = NBKT - 64; bb >= 0; bb -= 64) {
                const int2 c = ((const int2*)(ov.s_hist + bb))[lane];
                const int pair  = c.x + c.y;
                const int total = __reduce_add_sync(FULL, pair);
                if (cum + total >= KSEL) {
                    int suf = pair;          // inclusive suffix sum over lanes
#pragma unroll
                    for (int off = 1; off < 32; off <<= 1) {
                        const int o = __shfl_down_sync(FULL, suf, off);
                        if (lane + off < 32) suf += o;
                    }
                    const int cx = cum + suf;
                    const unsigned bal = __ballot_sync(FULL, cx >= KSEL);
                    const int hi = 31 - __clz(bal);
                    if (lane == hi) {
                        const int cy = cx - c.x;
                        s_bkt = bb + lane * 2 + ((cy >= KSEL) ? 1 : 0);
                    }
                    break;
                }
                cum += total;
            }
        }
        __syncthreads();   // s_bkt ready; hist dead (union -> keys)

        // ---- Gather: mapped compare; u-load + Gumbel key only for ~100 ----
        const unsigned thrm = fmap(unfmap((unsigned)s_bkt << 20) - MARGIN);
        const float* __restrict__ urow = u + (size_t)bm * NCOL;
#pragma unroll
        for (int j = 0; j < VPT; j++) {
            if (um[j] >= thrm) {
                const int pos = atomicAdd(&s_cnt, 1);
                if (pos < CAP) {
                    const int idx = base + j;
                    const float u2 = urow[idx];
                    const float gn = -0.001f * __logf(-__logf(u2 + 1e-20f) + 1e-20f);
                    const float val = unfmap(um[j]) + gn;
                    // unique key; larger value wins, ties -> lower index
                    ov.s_keys[pos] = ((unsigned long long)fmap(val) << 32)
                                   | (unsigned)(~idx);
                }
            }
        }
        __syncthreads();

        // ---- Parallel rank-count top-32 (all 256 threads) ----
        const int cnt = min(s_cnt, CAP);     // >= KSEL by construction
        for (int i = t; i < cnt; i += TPB) {
            const unsigned long long k = ov.s_keys[i];
            int r = 0;
            for (int j = 0; j < cnt; j++)
                r += (ov.s_keys[j] > k) ? 1 : 0;   // unique keys -> unique ranks
            if (r < KSEL) s_top[r] = (int)(~(unsigned)k);
        }
        __syncthreads();

        // ---- Index-rank sort -> ascending; publish + release flag ----
        if (t < KSEL) {
            const int myidx = s_top[t];
            int rank = 0;
#pragma unroll
            for (int j = 0; j < KSEL; j++) rank += (s_top[j] < myidx) ? 1 : 0;
            g_idx[bm * KSEL + rank] = myidx;
        }
        __syncthreads();                      // block-wide ordering of g_idx
        if (t == 0) atom_exch_release(&g_flag[bm], 1);   // publish
        return;                               // retire fast, free the slot
    }

    // ====================== FILL-ONLY block ================================
    const int f    = b - NPAIR;              // 0..16383
    const int bmf  = f & (NPAIR - 1);
    const int sub  = f >> 9;
    const int row  = bmf * KSEL + sub;

    // ---- Zeros: all 256 threads, 4 float4 each (identical to R1 fill) ----
    float4* __restrict__ o = reinterpret_cast<float4*>(out + (size_t)row * NCOL);
    const float4 z = make_float4(0.f, 0.f, 0.f, 0.f);
#pragma unroll
    for (int i = 0; i < 4; i++)
        o[t + i * TPB] = z;

    __syncthreads();                         // all zeros ordered into t0

    // ---- Tail: ONE acq_rel atomic; only the 32nd block per bm does more ----
    if (t < 32) {
        int old = 0;
        if (t == 0) old = atom_add_acqrel(&g_done[bmf], 1);
        old = __shfl_sync(0xffffffffu, old, 0);
        if (old == KSEL - 1) {
            // last fill block of this bm: all zeros of the bm are visible.
            if (t == 0) {
                int v = ld_acquire(&g_flag[bmf]);
                while (!v) { __nanosleep(32); v = ld_acquire(&g_flag[bmf]); }
            }
            __syncwarp();                    // order g_idx reads after acquire
            const int tgt = g_idx[bmf * KSEL + t];      // 32 lanes in parallel
            out[(size_t)(bmf * KSEL + t) * NCOL + tgt] = 1.0f;
            __syncwarp();
            if (t == 0) {                    // reset for next graph replay
                atomicExch(&g_flag[bmf], 0);
                atomicExch(&g_done[bmf], 0);
            }
        }
    }
}

extern "C" void kernel_launch(void* const* d_in, const int* in_sizes, int n_in,
                              void* d_out, int out_size)
{
    const float* logits = (const float*)d_in[0];   // (64, 4096) fp32
    const float* u      = (const float*)d_in[1];   // (8, 64, 4096) fp32
    float*       out    = (float*)d_out;           // (8, 64, 32, 4096) fp32

    fused_kernel<<<NPAIR + NROWS, TPB>>>(logits, u, out);
}

// round 17
// speedup vs baseline: 1.0842x; 1.0163x over previous
#include <cuda_runtime.h>
#include <cuda_bf16.h>
#include <math.h>

// Problem constants
#define BSZ   8
#define MROW  64
#define NCOL  4096
#define KSEL  32
#define NPAIR (BSZ * MROW)        // 512 (b,m) pairs
#define NROWS (NPAIR * KSEL)      // 16384 output rows
#define RPB   2                   // rows per fill block
#define NFILL (NROWS / RPB)       // 8192 fill blocks
#define NCONS (KSEL / RPB)        // 16 consumer blocks per bm
#define TPB   256                 // 8 warps
#define VPT   16                  // logits per thread (4096/256)
#define NBKT  4096                // histogram buckets (top 12 bits of fmap)
#define CAP   2048                // candidate cap (expected ~100)

// Noise bounds: gn = -0.001*log(-log(u+1e-20)+1e-20) in [-0.003830, +0.046052],
// span < 0.04989 -> margin 0.06 is strictly safe.
#define MARGIN 0.06f

// Static scratch (no allocation allowed). Self-cleaning across launches:
// g_flag/g_done return to 0 at the end of every launch (last-consumer reset).
__device__ int g_idx[NROWS];
__device__ int g_flag[NPAIR];
__device__ int g_done[NPAIR];

// Order-preserving float->uint map: a > b  <=>  fmap(a) > fmap(b). Bijective.
__device__ __forceinline__ unsigned fmap(float f) {
    unsigned b = __float_as_uint(f);
    return b ^ ((unsigned)(((int)b) >> 31) | 0x80000000u);
}
__device__ __forceinline__ float unfmap(unsigned m) {
    unsigned b = (m & 0x80000000u) ? (m ^ 0x80000000u) : ~m;
    return __uint_as_float(b);
}

// Scoped atomics (no CCTL.IVALL, unlike __threadfence)
__device__ __forceinline__ int atom_add_acqrel(int* p, int v) {
    int old;
    asm volatile("atom.acq_rel.gpu.global.add.s32 %0, [%1], %2;"
                 : "=r"(old) : "l"(p), "r"(v) : "memory");
    return old;
}
__device__ __forceinline__ void atom_exch_release(int* p, int v) {
    int old;
    asm volatile("atom.release.gpu.global.exch.b32 %0, [%1], %2;"
                 : "=r"(old) : "l"(p), "r"(v) : "memory");
}
__device__ __forceinline__ int ld_acquire(const int* p) {
    int v;
    asm volatile("ld.acquire.gpu.global.b32 %0, [%1];"
                 : "=r"(v) : "l"(p) : "memory");
    return v;
}

// ---------------------------------------------------------------------------
// Split-grid fused kernel: grid = NPAIR + NFILL.
//   blocks [0, 512):   SELECT-ONLY for bm = b; release flag; retire fast.
//   blocks [512, ...): FILL-ONLY, 2 adjacent rows (32 KB contiguous):
//                      zeros -> one acq_rel counter atomic. The LAST fill
//                      block per bm (old == NCONS-1) alone polls the flag and
//                      writes all 32 scattered 1.0s, then resets flag+counter
//                      (graph-replay safe).
// Ordering: each block's release-add orders its zeros before the increment;
// the last block's acquire-add synchronizes with all other releases, so every
// zero of the bm is visible before any 1.0 of the bm is stored.
// ---------------------------------------------------------------------------
__global__ __launch_bounds__(TPB, 8)
void fused_kernel(const float* __restrict__ logits,
                  const float* __restrict__ u,
                  float* __restrict__ out)
{
    const int b = blockIdx.x;
    const int t = threadIdx.x;

    if (b < NPAIR) {
        // =================== SELECT-ONLY for bm = b ========================
        // hist dead before keys are written -> overlay (16 KB), 16B-aligned
        // for the int4 zero-fill stores.
        __shared__ __align__(16) union {
            int                s_hist[NBKT];
            unsigned long long s_keys[CAP];
        } ov;
        __shared__ int s_top[KSEL];
        __shared__ int s_cnt;
        __shared__ int s_bkt;

        const int bm   = b;
        const int m    = bm & (MROW - 1);
        const int lane = t & 31;
        const int warp = t >> 5;

        // ---- Load logits row straight into mapped-uint domain ----
        const int base = t * VPT;
        const float4* __restrict__ l4 = (const float4*)(logits + (size_t)m * NCOL);
        unsigned um[VPT];
#pragma unroll
        for (int q = 0; q < 4; q++) {
            float4 ll = l4[(base >> 2) + q];
            um[q*4+0] = fmap(ll.x); um[q*4+1] = fmap(ll.y);
            um[q*4+2] = fmap(ll.z); um[q*4+3] = fmap(ll.w);
        }

        // ---- Zero histogram ----
#pragma unroll
        for (int i = 0; i < NBKT / (TPB * 4); i++)
            ((int4*)ov.s_hist)[t + i * TPB] = make_int4(0, 0, 0, 0);
        if (t == 0) s_cnt = 0;

        // ---- Prefilter: thread max only (1 atomic/thread; 256 counted real
        //      values >= 32 -> threshold conservative -> still exact) ----
        unsigned mx = um[0];
#pragma unroll
        for (int j = 1; j < VPT; j++) mx = max(mx, um[j]);
        __syncthreads();                     // hist zeroed
        atomicAdd(&ov.s_hist[mx >> 20], 1);
        __syncthreads();

        // ---- Warp 0: chunk scan for bucket where counted-cum reaches 32 ----
        if (warp == 0) {
            const unsigned FULL = 0xffffffffu;
            int cum = 0;
            for (int bb = NBKT - 64; bb >= 0; bb -= 64) {
                const int2 c = ((const int2*)(ov.s_hist + bb))[lane];
                const int pair  = c.x + c.y;
                const int total = __reduce_add_sync(FULL, pair);
                if (cum + total >= KSEL) {
                    int suf = pair;          // inclusive suffix sum over lanes
#pragma unroll
                    for (int off = 1; off < 32; off <<= 1) {
                        const int o = __shfl_down_sync(FULL, suf, off);
                        if (lane + off < 32) suf += o;
                    }
                    const int cx = cum + suf;
                    const unsigned bal = __ballot_sync(FULL, cx >= KSEL);
                    const int hi = 31 - __clz(bal);
                    if (lane == hi) {
                        const int cy = cx - c.x;
                        s_bkt = bb + lane * 2 + ((cy >= KSEL) ? 1 : 0);
                    }
                    break;
                }
                cum += total;
            }
        }
        __syncthreads();   // s_bkt ready; hist dead (union -> keys)

        // ---- Gather: mapped compare; u-load + Gumbel key only for ~100 ----
        const unsigned thrm = fmap(unfmap((unsigned)s_bkt << 20) - MARGIN);
        const float* __restrict__ urow = u + (size_t)bm * NCOL;
#pragma unroll
        for (int j = 0; j < VPT; j++) {
            if (um[j] >= thrm) {
                const int pos = atomicAdd(&s_cnt, 1);
                if (pos < CAP) {
                    const int idx = base + j;
                    const float u2 = urow[idx];
                    const float gn = -0.001f * __logf(-__logf(u2 + 1e-20f) + 1e-20f);
                    const float val = unfmap(um[j]) + gn;
                    // unique key; larger value wins, ties -> lower index
                    ov.s_keys[pos] = ((unsigned long long)fmap(val) << 32)
                                   | (unsigned)(~idx);
                }
            }
        }
        __syncthreads();

        // ---- Parallel rank-count top-32 (all 256 threads) ----
        const int cnt = min(s_cnt, CAP);     // >= KSEL by construction
        for (int i = t; i < cnt; i += TPB) {
            const unsigned long long k = ov.s_keys[i];
            int r = 0;
            for (int j = 0; j < cnt; j++)
                r += (ov.s_keys[j] > k) ? 1 : 0;   // unique keys -> unique ranks
            if (r < KSEL) s_top[r] = (int)(~(unsigned)k);
        }
        __syncthreads();

        // ---- Index-rank sort -> ascending; publish + release flag ----
        if (t < KSEL) {
            const int myidx = s_top[t];
            int rank = 0;
#pragma unroll
            for (int j = 0; j < KSEL; j++) rank += (s_top[j] < myidx) ? 1 : 0;
            g_idx[bm * KSEL + rank] = myidx;
        }
        __syncthreads();                      // block-wide ordering of g_idx
        if (t == 0) atom_exch_release(&g_flag[bm], 1);   // publish
        return;                               // retire fast, free the slot
    }

    // ====================== FILL-ONLY block: 2 adjacent rows ===============
    const int f    = b - NPAIR;              // 0..8191
    const int bmf  = f & (NPAIR - 1);
    const int sub  = (f >> 9) * RPB;         // first of 2 rows
    const int row0 = bmf * KSEL + sub;

    // ---- Zeros: 2048 float4 slots = 32 KB contiguous; 8 per thread ----
    float4* __restrict__ o = reinterpret_cast<float4*>(out + (size_t)row0 * NCOL);
    const float4 z = make_float4(0.f, 0.f, 0.f, 0.f);
#pragma unroll
    for (int i = 0; i < 2 * 4; i++)
        o[t + i * TPB] = z;

    __syncthreads();                         // all zeros ordered into t0

    // ---- Tail: ONE acq_rel atomic; only the last block per bm does more ----
    if (t < 32) {
        int old = 0;
        if (t == 0) old = atom_add_acqrel(&g_done[bmf], 1);
        old = __shfl_sync(0xffffffffu, old, 0);
        if (old == NCONS - 1) {
            // last fill block of this bm: all zeros of the bm are visible.
            if (t == 0) {
                int v = ld_acquire(&g_flag[bmf]);
                while (!v) { __nanosleep(32); v = ld_acquire(&g_flag[bmf]); }
            }
            __syncwarp();                    // order g_idx reads after acquire
            const int tgt = g_idx[bmf * KSEL + t];      // 32 lanes in parallel
            out[(size_t)(bmf * KSEL + t) * NCOL + tgt] = 1.0f;
            __syncwarp();
            if (t == 0) {                    // reset for next graph replay
                atomicExch(&g_flag[bmf], 0);
                atomicExch(&g_done[bmf], 0);
            }
        }
    }
}

extern "C" void kernel_launch(void* const* d_in, const int* in_sizes, int n_in,
                              void* d_out, int out_size)
{
    const float* logits = (const float*)d_in[0];   // (64, 4096) fp32
    const float* u      = (const float*)d_in[1];   // (8, 64, 4096) fp32
    float*       out    = (float*)d_out;           // (8, 64, 32, 4096) fp32

    fused_kernel<<<NPAIR + NFILL, TPB>>>(logits, u, out);
}